// round 10
// baseline (speedup 1.0000x reference)
#include <cuda_runtime.h>
#include <cuda_bf16.h>
#include <cstdint>

// Problem shape (fixed by reference setup_inputs)
#define B_    16
#define C_    384
#define CR_   96
#define HW_   12544          // 112*112
#define HW4_  3136           // HW/4 (float4 per plane); 3136 = 448*7 exactly
#define NPLANES_ (B_ * C_)   // 6144
#define T_    448
#define K_    7
#define FCW_  12             // warps in fc kernel (384 threads)

#define HALF_B_   8
#define HPLANES_  (HALF_B_ * C_)   // 3072

// Scratch (no cudaMalloc allowed) — device globals.
__device__ float g_mean[NPLANES_];
__device__ float g_scale[NPLANES_];

// ---------------------------------------------------------------------------
// Kernel 1: per-plane mean for one 8-batch half (3072 CTAs, full ramp size).
// ---------------------------------------------------------------------------
__global__ void __launch_bounds__(T_) se_reduce_kernel(const float* __restrict__ x,
                                                       int b0) {
    const int plane = b0 * C_ + blockIdx.x;
    const float4* __restrict__ p =
        reinterpret_cast<const float4*>(x) + (size_t)plane * HW4_;

    float4 v[K_];
    #pragma unroll
    for (int k = 0; k < K_; k++)
        v[k] = p[threadIdx.x + k * T_];

    float sum = 0.0f;
    #pragma unroll
    for (int k = 0; k < K_; k++)
        sum += (v[k].x + v[k].y) + (v[k].z + v[k].w);

    #pragma unroll
    for (int o = 16; o > 0; o >>= 1)
        sum += __shfl_down_sync(0xffffffffu, sum, o);

    __shared__ float sdata[T_ / 32];
    const int lane = threadIdx.x & 31;
    const int wid  = threadIdx.x >> 5;
    if (lane == 0) sdata[wid] = sum;
    __syncthreads();
    if (wid == 0) {
        sum = (lane < (T_ / 32)) ? sdata[lane] : 0.0f;
        #pragma unroll
        for (int o = 8; o > 0; o >>= 1)
            sum += __shfl_down_sync(0xffffffffu, sum, o);
        if (lane == 0) g_mean[plane] = sum * (1.0f / (float)HW_);
    }
}

// ---------------------------------------------------------------------------
// Kernel 2: warp-cooperative FC chain for one half (8 CTAs x 384 thr, ~2us).
// ---------------------------------------------------------------------------
__global__ void __launch_bounds__(C_) se_fc_kernel(const float* __restrict__ w1,
                                                   const float* __restrict__ b1,
                                                   const float* __restrict__ w2,
                                                   const float* __restrict__ b2,
                                                   int b0) {
    const int b    = b0 + blockIdx.x;
    const int tid  = threadIdx.x;
    const int lane = tid & 31;
    const int wid  = tid >> 5;

    __shared__ float s[C_];
    __shared__ float t[CR_];

    s[tid] = g_mean[b * C_ + tid];
    __syncthreads();

    // Phase 1: warp per row, coalesced float4 weight loads.
    for (int r = wid; r < CR_; r += FCW_) {
        const float4* __restrict__ wr4 =
            reinterpret_cast<const float4*>(w1 + r * C_);
        float acc = 0.0f;
        #pragma unroll
        for (int k = 0; k < 3; k++) {
            const int i4 = lane + 32 * k;
            const float4 wv = __ldg(&wr4[i4]);
            const int c = i4 * 4;
            acc = fmaf(wv.x, s[c + 0], acc);
            acc = fmaf(wv.y, s[c + 1], acc);
            acc = fmaf(wv.z, s[c + 2], acc);
            acc = fmaf(wv.w, s[c + 3], acc);
        }
        #pragma unroll
        for (int o = 16; o > 0; o >>= 1)
            acc += __shfl_down_sync(0xffffffffu, acc, o);
        if (lane == 0) t[r] = fmaxf(acc + __ldg(&b1[r]), 0.0f);
    }
    __syncthreads();

    // Phase 2: warp per output channel, coalesced scalar loads.
    for (int c = wid; c < C_; c += FCW_) {
        const float* __restrict__ wc = w2 + c * CR_;
        float acc = 0.0f;
        #pragma unroll
        for (int k = 0; k < 3; k++) {
            const int r = lane + 32 * k;
            acc = fmaf(__ldg(&wc[r]), t[r], acc);
        }
        #pragma unroll
        for (int o = 16; o > 0; o >>= 1)
            acc += __shfl_down_sync(0xffffffffu, acc, o);
        if (lane == 0)
            g_scale[b * C_ + c] =
                __saturatef(fmaf(acc + __ldg(&b2[c]), 1.0f / 6.0f, 0.5f));
    }
}

// ---------------------------------------------------------------------------
// Kernel 3: scale one half; reverse plane order within the half (the half's
// tail is the part most recently read by its reduce). Streaming hints.
// ---------------------------------------------------------------------------
__global__ void __launch_bounds__(T_) se_scale_kernel(const float* __restrict__ x,
                                                      float* __restrict__ out,
                                                      int b0) {
    const int plane = b0 * C_ + (HPLANES_ - 1 - blockIdx.x);
    const float sc = g_scale[plane];
    const float4* __restrict__ p =
        reinterpret_cast<const float4*>(x) + (size_t)plane * HW4_;
    float4* __restrict__ o =
        reinterpret_cast<float4*>(out) + (size_t)plane * HW4_;

    float4 v[K_];
    #pragma unroll
    for (int k = 0; k < K_; k++)
        v[k] = __ldcs(&p[threadIdx.x + k * T_]);

    #pragma unroll
    for (int k = 0; k < K_; k++) {
        v[k].x *= sc; v[k].y *= sc; v[k].z *= sc; v[k].w *= sc;
        __stcs(&o[threadIdx.x + k * T_], v[k]);
    }
}

// ---------------------------------------------------------------------------
// Two-stream overlapped schedule (6 kernel nodes):
//   main:  reduce(H0) fc(H0) [e1]  reduce(H1) fc(H1) [e2]
//   side:  wait e1  scale(H0)      wait e2  scale(H1)   [join]
// scale(H0) overlaps reduce(H1). fc is now ~2us so it no longer poisons
// the critical path (the R8 failure mode).
// ---------------------------------------------------------------------------
extern "C" void kernel_launch(void* const* d_in, const int* in_sizes, int n_in,
                              void* d_out, int out_size) {
    const float* x  = (const float*)d_in[0];
    const float* w1 = (const float*)d_in[1];
    const float* b1 = (const float*)d_in[2];
    const float* w2 = (const float*)d_in[3];
    const float* b2 = (const float*)d_in[4];
    float* out = (float*)d_out;

    static cudaStream_t s1 = nullptr;
    static cudaEvent_t  e1 = nullptr, e2 = nullptr, eJoin = nullptr;
    if (s1 == nullptr) {
        cudaStreamCreateWithFlags(&s1, cudaStreamNonBlocking);
        cudaEventCreateWithFlags(&e1,    cudaEventDisableTiming);
        cudaEventCreateWithFlags(&e2,    cudaEventDisableTiming);
        cudaEventCreateWithFlags(&eJoin, cudaEventDisableTiming);
    }

    se_reduce_kernel<<<HPLANES_, T_, 0, 0>>>(x, 0);
    se_fc_kernel<<<HALF_B_, C_, 0, 0>>>(w1, b1, w2, b2, 0);
    cudaEventRecord(e1, 0);

    se_reduce_kernel<<<HPLANES_, T_, 0, 0>>>(x, HALF_B_);
    se_fc_kernel<<<HALF_B_, C_, 0, 0>>>(w1, b1, w2, b2, HALF_B_);
    cudaEventRecord(e2, 0);

    cudaStreamWaitEvent(s1, e1, 0);
    se_scale_kernel<<<HPLANES_, T_, 0, s1>>>(x, out, 0);
    cudaStreamWaitEvent(s1, e2, 0);
    se_scale_kernel<<<HPLANES_, T_, 0, s1>>>(x, out, HALF_B_);

    cudaEventRecord(eJoin, s1);
    cudaStreamWaitEvent(0, eJoin, 0);
}

// round 11
// speedup vs baseline: 1.3190x; 1.3190x over previous
#include <cuda_runtime.h>
#include <cuda_bf16.h>
#include <cstdint>

// Problem shape (fixed by reference setup_inputs)
#define B_    16
#define C_    384
#define CR_   96
#define HW_   12544          // 112*112
#define HW4_  3136           // HW/4 (float4 per plane); 3136 = 448*7 exactly
#define NPLANES_ (B_ * C_)   // 6144
#define T_    448
#define K_    7

// Scratch (no cudaMalloc allowed) — device globals.
__device__ float g_mean[NPLANES_];
__device__ float g_t[B_ * CR_];
__device__ float g_scale[NPLANES_];

// ---------------------------------------------------------------------------
// Kernel 1: per-plane mean. One CTA per plane. At DRAM roofline (82-84%).
// ---------------------------------------------------------------------------
__global__ void __launch_bounds__(T_) se_reduce_kernel(const float* __restrict__ x) {
    const int plane = blockIdx.x;
    const float4* __restrict__ p =
        reinterpret_cast<const float4*>(x) + (size_t)plane * HW4_;

    float4 v[K_];
    #pragma unroll
    for (int k = 0; k < K_; k++)
        v[k] = p[threadIdx.x + k * T_];

    float sum = 0.0f;
    #pragma unroll
    for (int k = 0; k < K_; k++)
        sum += (v[k].x + v[k].y) + (v[k].z + v[k].w);

    #pragma unroll
    for (int o = 16; o > 0; o >>= 1)
        sum += __shfl_down_sync(0xffffffffu, sum, o);

    __shared__ float sdata[T_ / 32];
    const int lane = threadIdx.x & 31;
    const int wid  = threadIdx.x >> 5;
    if (lane == 0) sdata[wid] = sum;
    __syncthreads();
    if (wid == 0) {
        sum = (lane < (T_ / 32)) ? sdata[lane] : 0.0f;
        #pragma unroll
        for (int o = 8; o > 0; o >>= 1)
            sum += __shfl_down_sync(0xffffffffu, sum, o);
        if (lane == 0) g_mean[plane] = sum * (1.0f / (float)HW_);
    }
}

// ---------------------------------------------------------------------------
// Kernel 2a: fc1 — one warp per (b,r) dot, NO per-warp loop.
// 1536 dots total -> 384 CTAs x 4 warps. Each lane: 3 float4 loads of w1 and
// mean, 12 FMAs, warp reduce. All load latency is paid in parallel grid-wide.
// ---------------------------------------------------------------------------
__global__ void __launch_bounds__(128) se_fc1_kernel(const float* __restrict__ w1,
                                                     const float* __restrict__ b1) {
    const int lane = threadIdx.x & 31;
    const int d    = blockIdx.x * 4 + (threadIdx.x >> 5);   // 0..1535
    const int b    = d / CR_;
    const int r    = d % CR_;

    const float4* __restrict__ wr4 =
        reinterpret_cast<const float4*>(w1 + r * C_);       // 96 float4
    const float4* __restrict__ sb4 =
        reinterpret_cast<const float4*>(g_mean + b * C_);   // 96 float4

    float acc = 0.0f;
    #pragma unroll
    for (int k = 0; k < 3; k++) {
        const int i4 = lane + 32 * k;
        const float4 wv = __ldg(&wr4[i4]);
        const float4 sv = sb4[i4];
        acc = fmaf(wv.x, sv.x, acc);
        acc = fmaf(wv.y, sv.y, acc);
        acc = fmaf(wv.z, sv.z, acc);
        acc = fmaf(wv.w, sv.w, acc);
    }
    #pragma unroll
    for (int o = 16; o > 0; o >>= 1)
        acc += __shfl_down_sync(0xffffffffu, acc, o);
    if (lane == 0) g_t[d] = fmaxf(acc + __ldg(&b1[r]), 0.0f);
}

// ---------------------------------------------------------------------------
// Kernel 2b: fc2 — one warp per (b,c) dot, NO per-warp loop.
// 6144 dots total -> 1536 CTAs x 4 warps. Each lane: 3 scalar loads of w2/t.
// ---------------------------------------------------------------------------
__global__ void __launch_bounds__(128) se_fc2_kernel(const float* __restrict__ w2,
                                                     const float* __restrict__ b2) {
    const int lane = threadIdx.x & 31;
    const int d    = blockIdx.x * 4 + (threadIdx.x >> 5);   // 0..6143
    const int b    = d / C_;
    const int c    = d % C_;

    const float* __restrict__ wc = w2 + c * CR_;
    const float* __restrict__ tb = g_t + b * CR_;

    float acc = 0.0f;
    #pragma unroll
    for (int k = 0; k < 3; k++) {
        const int r = lane + 32 * k;
        acc = fmaf(__ldg(&wc[r]), tb[r], acc);
    }
    #pragma unroll
    for (int o = 16; o > 0; o >>= 1)
        acc += __shfl_down_sync(0xffffffffu, acc, o);
    if (lane == 0)
        g_scale[b * C_ + c] =
            __saturatef(fmaf(acc + __ldg(&b2[c]), 1.0f / 6.0f, 0.5f));
}

// ---------------------------------------------------------------------------
// Kernel 3: broadcast multiply. Reverse plane order (L2-hot tail first),
// streaming hints. ~6.9 TB/s effective — at the mixed r+w roofline.
// ---------------------------------------------------------------------------
__global__ void __launch_bounds__(T_) se_scale_kernel(const float* __restrict__ x,
                                                      float* __restrict__ out) {
    const int plane = (NPLANES_ - 1) - blockIdx.x;
    const float sc = g_scale[plane];
    const float4* __restrict__ p =
        reinterpret_cast<const float4*>(x) + (size_t)plane * HW4_;
    float4* __restrict__ o =
        reinterpret_cast<float4*>(out) + (size_t)plane * HW4_;

    float4 v[K_];
    #pragma unroll
    for (int k = 0; k < K_; k++)
        v[k] = __ldcs(&p[threadIdx.x + k * T_]);

    #pragma unroll
    for (int k = 0; k < K_; k++) {
        v[k].x *= sc; v[k].y *= sc; v[k].z *= sc; v[k].w *= sc;
        __stcs(&o[threadIdx.x + k * T_], v[k]);
    }
}

// ---------------------------------------------------------------------------
extern "C" void kernel_launch(void* const* d_in, const int* in_sizes, int n_in,
                              void* d_out, int out_size) {
    const float* x  = (const float*)d_in[0];
    const float* w1 = (const float*)d_in[1];
    const float* b1 = (const float*)d_in[2];
    const float* w2 = (const float*)d_in[3];
    const float* b2 = (const float*)d_in[4];
    float* out = (float*)d_out;

    se_reduce_kernel<<<NPLANES_, T_>>>(x);
    se_fc1_kernel<<<(B_ * CR_) / 4, 128>>>(w1, b1);
    se_fc2_kernel<<<(B_ * C_) / 4, 128>>>(w2, b2);
    se_scale_kernel<<<NPLANES_, T_>>>(x, out);
}